// round 10
// baseline (speedup 1.0000x reference)
#include <cuda_runtime.h>
#include <cuda_fp16.h>
#include <math.h>
#include <stdint.h>

// Problem constants (fixed by setup_inputs)
#define DIM   256
#define NHEAD 8
#define DHEAD 32
#define LQ    16320
#define PROJN 768   // [cso 256 | tso 256 | caw 128 | taw 128]

// Scratch (device globals)
__device__ __half g_value[LQ * DIM];
__device__ float  g_proj [LQ * PROJN];
__device__ __half g_mid  [LQ * DIM];

// ---------------- FP16 tensor-core GEMM v5 (m16n8k16, double-buffered) -----
// C = A(M x 256) * B(256 x N) + bias, fp32 accum. Block tile 64x128, BK=32.
// 256 threads = 8 warps (2x4), warp tile 32x32 = 2x4 m16n8k16 atoms.
// 2-stage smem pipeline: one __syncthreads per 32-k slab.
#define GBM 64
#define GBN 128
#define AROW 40    // halfs per A row (32 + 8 pad)
#define BROW 136   // halfs per B row (128 + 8 pad)
#define ABUF (64 * AROW)
#define BBUF (32 * BROW)

struct Seg {
    const void*  A;      // float* or __half* (template)
    const float* B;
    const float* bias;
    float*  Cf;
    __half* Ch;
    int ldb, boff, ldc, cn0, ishalf;
};
struct SegArr { Seg s[8]; };

__device__ __forceinline__ uint32_t pack2(float a, float b) {
    __half2 h = __floats2half2_rn(a, b);
    return *(uint32_t*)&h;
}
__device__ __forceinline__ uint4 pack8(float4 v0, float4 v1) {
    uint4 u;
    u.x = pack2(v0.x, v0.y); u.y = pack2(v0.z, v0.w);
    u.z = pack2(v1.x, v1.y); u.w = pack2(v1.z, v1.w);
    return u;
}
__device__ __forceinline__ void ldsm4(uint32_t* r, uint32_t addr) {
    asm volatile("ldmatrix.sync.aligned.m8n8.x4.shared.b16 {%0,%1,%2,%3}, [%4];"
        : "=r"(r[0]), "=r"(r[1]), "=r"(r[2]), "=r"(r[3]) : "r"(addr));
}
__device__ __forceinline__ void ldsm4t(uint32_t* r, uint32_t addr) {
    asm volatile("ldmatrix.sync.aligned.m8n8.x4.trans.shared.b16 {%0,%1,%2,%3}, [%4];"
        : "=r"(r[0]), "=r"(r[1]), "=r"(r[2]), "=r"(r[3]) : "r"(addr));
}

template <typename AT>
__global__ __launch_bounds__(256) void mma_gemm_seg(SegArr sa)
{
    __shared__ __half As[2 * ABUF];   // 10240 B
    __shared__ __half Bs[2 * BBUF];   // 17408 B

    const Seg sg = sa.s[blockIdx.x];
    const int tid = threadIdx.x;
    const int bm  = blockIdx.y * GBM;

    const int lane = tid & 31, wid = tid >> 5;
    const int wm = wid >> 2, wn = wid & 3;
    const int g = lane >> 2, t = lane & 3;

    // ---- fill mappings ----
    const int ar = tid >> 2;            // A row 0..63
    const int ak = (tid & 3) << 3;      // A col octet base (8 halfs / 8 floats)
    const AT* Ag = (const AT*)sg.A + (size_t)(bm + ar) * 256 + ak;
    const int as_off = ar * AROW + ak;

    const int bkr = tid >> 4;           // B k-row 0..15 (2 iters: +0, +16)
    const int bn  = (tid & 15) << 3;    // B col octet
    const float* Bg = sg.B + (size_t)bkr * sg.ldb + sg.boff + bn;
    const int bs_off = bkr * BROW + bn;

    // ---- ldmatrix lane addresses ----
    const uint32_t as_addr = (uint32_t)__cvta_generic_to_shared(As);
    const uint32_t bs_addr = (uint32_t)__cvta_generic_to_shared(Bs);
    const int arow = wm * 32 + (lane & 7) + ((lane >> 3) & 1) * 8;  // + mi*16
    const int acol = (lane >> 4) * 8;                                // + ks*16
    const int brow = (lane & 7) + ((lane >> 3) & 1) * 8;             // + ks*16
    const int bcol = wn * 32 + (lane >> 4) * 8;                      // + nip*16
    const uint32_t aaddr0 = as_addr + (uint32_t)((arow * AROW + acol) * 2);
    const uint32_t baddr0 = bs_addr + (uint32_t)((brow * BROW + bcol) * 2);

    float acc[2][4][4] = {};

    // prefetch/store helpers (manual, unrolled by the k0 loop)
    uint4 a_st;                 // packed 8 halfs for A
    uint4 b_st[2];              // packed 8 halfs x2 for B

    // ---- load slab 0 ----
    if constexpr (sizeof(AT) == 4) {
        float4 v0 = *(const float4*)(Ag);
        float4 v1 = *(const float4*)(Ag + 4);
        a_st = pack8(v0, v1);
    } else {
        a_st = *(const uint4*)(Ag);
    }
    #pragma unroll
    for (int it = 0; it < 2; ++it) {
        const float* p = Bg + (size_t)(it * 16) * sg.ldb;
        b_st[it] = pack8(*(const float4*)(p), *(const float4*)(p + 4));
    }
    *(uint4*)(As + as_off) = a_st;
    #pragma unroll
    for (int it = 0; it < 2; ++it)
        *(uint4*)(Bs + bs_off + it * 16 * BROW) = b_st[it];
    __syncthreads();

    #pragma unroll
    for (int s = 0; s < 8; ++s) {
        const int cur = s & 1;
        // prefetch slab s+1 (LDG early, consumed after MMA)
        if (s < 7) {
            const int k0 = (s + 1) * 32;
            if constexpr (sizeof(AT) == 4) {
                float4 v0 = *(const float4*)(Ag + k0);
                float4 v1 = *(const float4*)(Ag + k0 + 4);
                a_st = pack8(v0, v1);
            } else {
                a_st = *(const uint4*)(Ag + k0);
            }
            #pragma unroll
            for (int it = 0; it < 2; ++it) {
                const float* p = Bg + (size_t)(k0 + it * 16) * sg.ldb;
                b_st[it] = pack8(*(const float4*)(p), *(const float4*)(p + 4));
            }
        }

        // MMAs on buffer `cur`
        const uint32_t ab = aaddr0 + (uint32_t)(cur * ABUF * 2);
        const uint32_t bb = baddr0 + (uint32_t)(cur * BBUF * 2);
        #pragma unroll
        for (int ks = 0; ks < 2; ++ks) {
            uint32_t a[2][4], b[2][4];
            #pragma unroll
            for (int mi = 0; mi < 2; ++mi)
                ldsm4(a[mi], ab + (uint32_t)((mi * 16 * AROW + ks * 16) * 2));
            #pragma unroll
            for (int nip = 0; nip < 2; ++nip)
                ldsm4t(b[nip], bb + (uint32_t)((ks * 16 * BROW + nip * 16) * 2));
            #pragma unroll
            for (int mi = 0; mi < 2; ++mi)
                #pragma unroll
                for (int ni = 0; ni < 4; ++ni) {
                    uint32_t b0 = b[ni >> 1][(ni & 1) * 2];
                    uint32_t b1 = b[ni >> 1][(ni & 1) * 2 + 1];
                    asm volatile(
                        "mma.sync.aligned.m16n8k16.row.col.f32.f16.f16.f32 "
                        "{%0,%1,%2,%3}, {%4,%5,%6,%7}, {%8,%9}, {%0,%1,%2,%3};"
                        : "+f"(acc[mi][ni][0]), "+f"(acc[mi][ni][1]),
                          "+f"(acc[mi][ni][2]), "+f"(acc[mi][ni][3])
                        : "r"(a[mi][0]), "r"(a[mi][1]), "r"(a[mi][2]), "r"(a[mi][3]),
                          "r"(b0), "r"(b1));
                }
        }

        // store slab s+1 into the other buffer, then one sync
        if (s < 7) {
            const int nxt = cur ^ 1;
            *(uint4*)(As + nxt * ABUF + as_off) = a_st;
            #pragma unroll
            for (int it = 0; it < 2; ++it)
                *(uint4*)(Bs + nxt * BBUF + bs_off + it * 16 * BROW) = b_st[it];
            __syncthreads();
        }
    }

    // ---- epilogue ----
    #pragma unroll
    for (int mi = 0; mi < 2; ++mi) {
        int row0 = bm + wm * 32 + mi * 16 + g;
        #pragma unroll
        for (int ni = 0; ni < 4; ++ni) {
            int lcol = wn * 32 + ni * 8 + t * 2;
            float2 bv2 = *(const float2*)(sg.bias + sg.boff + lcol);
            float v00 = acc[mi][ni][0] + bv2.x, v01 = acc[mi][ni][1] + bv2.y;
            float v10 = acc[mi][ni][2] + bv2.x, v11 = acc[mi][ni][3] + bv2.y;
            if (sg.ishalf) {
                *(__half2*)(sg.Ch + (size_t)row0 * sg.ldc + sg.cn0 + lcol)       = __floats2half2_rn(v00, v01);
                *(__half2*)(sg.Ch + (size_t)(row0 + 8) * sg.ldc + sg.cn0 + lcol) = __floats2half2_rn(v10, v11);
            } else {
                *(float2*)(sg.Cf + (size_t)row0 * sg.ldc + sg.cn0 + lcol)       = make_float2(v00, v01);
                *(float2*)(sg.Cf + (size_t)(row0 + 8) * sg.ldc + sg.cn0 + lcol) = make_float2(v10, v11);
            }
        }
    }
}

// ---------------- Deformable sampling + softmax (v3; fp16 mid out) ---------
__global__ __launch_bounds__(256) void deform_kernel(
    const float* __restrict__ proj,
    const __half* __restrict__ value,
    const float* __restrict__ refp,
    const float* __restrict__ toff,
    __half* __restrict__ mid)
{
    __shared__ float4 smw[256];
    __shared__ int4   sma[256];

    const int q    = blockIdx.x;
    const int warp = threadIdx.x >> 5;
    const int lane = threadIdx.x & 31;
    const int h = warp;
    const int l = lane >> 3;
    const int p = lane & 7;

    const int   Wl[4]  = {64, 32, 16, 8};
    const int   THl[4] = {192, 96, 48, 24};
    const int   STl[4] = {0, 12288, 15360, 16128};
    const int   Wv = Wl[l], TH = THl[l], start = STl[l];
    const float invW = 1.0f / (float)Wv, invTH = 1.0f / (float)TH;

    const float* prow = proj + (size_t)q * PROJN;

    int logit_col = (p < 4) ? (512 + h * 16 + l * 4 + p)
                            : (640 + h * 16 + l * 4 + (p - 4));
    float logit = prow[logit_col];
    float mx = logit;
    #pragma unroll
    for (int off = 16; off; off >>= 1) mx = fmaxf(mx, __shfl_xor_sync(0xffffffffu, mx, off));
    float e = __expf(logit - mx);
    float s = e;
    #pragma unroll
    for (int off = 16; off; off >>= 1) s += __shfl_xor_sync(0xffffffffu, s, off);
    float attnw = e / s;

    float rx = refp[q * 8 + l * 2 + 0];
    float ry = refp[q * 8 + l * 2 + 1];
    float ox, oy;
    if (p < 4) {
        int col = ((h * 4 + l) * 4 + p) * 2;
        ox = prow[col + 0] * invW;
        oy = prow[col + 1] * invTH;
    } else {
        int tw = (p - 4) >> 1, tp = (p - 4) & 1;
        int col = 256 + (((h * 4 + l) * 2 + tw) * 2 + tp) * 2;
        int tob = ((q * 4 + l) * 2 + tw) * 2;
        ox = toff[tob + 0] + prow[col + 0] * invW;
        oy = toff[tob + 1] + prow[col + 1] * invTH;
    }
    float x = (rx + ox) * (float)Wv - 0.5f;
    float y = (ry + oy) * (float)TH - 0.5f;

    float x0f = floorf(x), y0f = floorf(y);
    float lx = x - x0f, ly = y - y0f;
    int x0 = (int)x0f, y0 = (int)y0f;
    int x1 = x0 + 1,   y1 = y0 + 1;

    bool ix0 = (x0 >= 0) & (x0 < Wv);
    bool ix1 = (x1 >= 0) & (x1 < Wv);
    bool iy0 = (y0 >= 0) & (y0 < TH);
    bool iy1 = (y1 >= 0) & (y1 < TH);
    int cx0 = min(max(x0, 0), Wv - 1);
    int cx1 = min(max(x1, 0), Wv - 1);
    int cy0 = min(max(y0, 0), TH - 1);
    int cy1 = min(max(y1, 0), TH - 1);

    float4 w;
    w.x = attnw * (1.f - lx) * (1.f - ly) * (float)(ix0 & iy0);
    w.y = attnw * lx         * (1.f - ly) * (float)(ix1 & iy0);
    w.z = attnw * (1.f - lx) * ly         * (float)(ix0 & iy1);
    w.w = attnw * lx         * ly         * (float)(ix1 & iy1);

    const int hbase = h * DHEAD;
    int4 a;
    a.x = (start + cy0 * Wv + cx0) * DIM + hbase;
    a.y = (start + cy0 * Wv + cx1) * DIM + hbase;
    a.z = (start + cy1 * Wv + cx0) * DIM + hbase;
    a.w = (start + cy1 * Wv + cx1) * DIM + hbase;

    smw[threadIdx.x] = w;
    sma[threadIdx.x] = a;
    __syncwarp();

    const int p2 = lane >> 4;
    const int c  = (lane >> 2) & 3;
    const int o  = lane & 3;
    const int ob = o << 3;

    const int* aw_i   = (const int*)sma;
    const float* aw_f = (const float*)smw;
    const int sbase4 = (warp << 5) << 2;

    float acc[8] = {};
    #pragma unroll
    for (int i = 0; i < 16; ++i) {
        int widx = sbase4 + ((i * 2 + p2) << 2) + c;
        int   addr = aw_i[widx];
        float wgt  = aw_f[widx];
        uint4 v = __ldcg((const uint4*)(value + addr + ob));
        float2 f0 = __half22float2(*(__half2*)&v.x);
        float2 f1 = __half22float2(*(__half2*)&v.y);
        float2 f2 = __half22float2(*(__half2*)&v.z);
        float2 f3 = __half22float2(*(__half2*)&v.w);
        acc[0] += wgt * f0.x; acc[1] += wgt * f0.y;
        acc[2] += wgt * f1.x; acc[3] += wgt * f1.y;
        acc[4] += wgt * f2.x; acc[5] += wgt * f2.y;
        acc[6] += wgt * f3.x; acc[7] += wgt * f3.y;
    }
    #pragma unroll
    for (int j = 0; j < 8; ++j) {
        acc[j] += __shfl_xor_sync(0xffffffffu, acc[j], 4);
        acc[j] += __shfl_xor_sync(0xffffffffu, acc[j], 8);
        acc[j] += __shfl_xor_sync(0xffffffffu, acc[j], 16);
    }
    if (lane < 4) {
        uint4 o8;
        o8.x = pack2(acc[0], acc[1]);
        o8.y = pack2(acc[2], acc[3]);
        o8.z = pack2(acc[4], acc[5]);
        o8.w = pack2(acc[6], acc[7]);
        *(uint4*)(mid + (size_t)q * DIM + hbase + (lane << 3)) = o8;
    }
}

// ---------------- launch ----------------
extern "C" void kernel_launch(void* const* d_in, const int* in_sizes, int n_in,
                              void* d_out, int out_size)
{
    const float* query = (const float*)d_in[0];
    const float* refp  = (const float*)d_in[1];
    const float* toff  = (const float*)d_in[2];
    const float* inpf  = (const float*)d_in[3];
    const float* W_so  = (const float*)d_in[6];
    const float* b_so  = (const float*)d_in[7];
    const float* W_tso = (const float*)d_in[8];
    const float* b_tso = (const float*)d_in[9];
    const float* W_aw  = (const float*)d_in[10];
    const float* b_aw  = (const float*)d_in[11];
    const float* W_taw = (const float*)d_in[12];
    const float* b_taw = (const float*)d_in[13];
    const float* W_v   = (const float*)d_in[14];
    const float* b_v   = (const float*)d_in[15];
    const float* W_o   = (const float*)d_in[16];
    const float* b_o   = (const float*)d_in[17];
    float* out = (float*)d_out;

    __half *value, *mid; float *proj;
    cudaGetSymbolAddress((void**)&value, g_value);
    cudaGetSymbolAddress((void**)&proj,  g_proj);
    cudaGetSymbolAddress((void**)&mid,   g_mid);

    const int MB = LQ / GBM;  // 255
    dim3 blk(256);

    // (1) fused value + projections GEMM (8 segments, fp32 A)
    {
        SegArr sa{};
        for (int i = 0; i < 2; ++i) {
            sa.s[i].A = inpf; sa.s[i].B = W_v; sa.s[i].bias = b_v;
            sa.s[i].Ch = value; sa.s[i].ldb = 256; sa.s[i].boff = i * 128;
            sa.s[i].ldc = DIM; sa.s[i].cn0 = i * 128; sa.s[i].ishalf = 1;
        }
        for (int i = 0; i < 2; ++i) {
            sa.s[2 + i].A = query; sa.s[2 + i].B = W_so; sa.s[2 + i].bias = b_so;
            sa.s[2 + i].Cf = proj; sa.s[2 + i].ldb = 256; sa.s[2 + i].boff = i * 128;
            sa.s[2 + i].ldc = PROJN; sa.s[2 + i].cn0 = i * 128; sa.s[2 + i].ishalf = 0;
            sa.s[4 + i].A = query; sa.s[4 + i].B = W_tso; sa.s[4 + i].bias = b_tso;
            sa.s[4 + i].Cf = proj; sa.s[4 + i].ldb = 256; sa.s[4 + i].boff = i * 128;
            sa.s[4 + i].ldc = PROJN; sa.s[4 + i].cn0 = 256 + i * 128; sa.s[4 + i].ishalf = 0;
        }
        sa.s[6].A = query; sa.s[6].B = W_aw; sa.s[6].bias = b_aw;
        sa.s[6].Cf = proj; sa.s[6].ldb = 128; sa.s[6].boff = 0;
        sa.s[6].ldc = PROJN; sa.s[6].cn0 = 512; sa.s[6].ishalf = 0;
        sa.s[7].A = query; sa.s[7].B = W_taw; sa.s[7].bias = b_taw;
        sa.s[7].Cf = proj; sa.s[7].ldb = 128; sa.s[7].boff = 0;
        sa.s[7].ldc = PROJN; sa.s[7].cn0 = 640; sa.s[7].ishalf = 0;
        mma_gemm_seg<float><<<dim3(8, MB), blk>>>(sa);
    }
    // (2) deform (writes fp16 mid)
    deform_kernel<<<LQ, 256>>>(proj, value, refp, toff, mid);
    // (3) out = mid @ W_o + b_o  (fp16 A)
    {
        SegArr sa{};
        for (int i = 0; i < 2; ++i) {
            sa.s[i].A = mid; sa.s[i].B = W_o; sa.s[i].bias = b_o;
            sa.s[i].Cf = out; sa.s[i].ldb = 256; sa.s[i].boff = i * 128;
            sa.s[i].ldc = DIM; sa.s[i].cn0 = i * 128; sa.s[i].ishalf = 0;
        }
        mma_gemm_seg<__half><<<dim3(2, MB), blk>>>(sa);
    }
}

// round 11
// speedup vs baseline: 1.0395x; 1.0395x over previous
#include <cuda_runtime.h>
#include <cuda_fp16.h>
#include <math.h>
#include <stdint.h>

// Problem constants (fixed by setup_inputs)
#define DIM   256
#define NHEAD 8
#define DHEAD 32
#define LQ    16320
#define PROJN 768   // [cso 256 | tso 256 | caw 128 | taw 128]

// Head-major value, two alignment copies.
// Copy A: pixel p at slot p+1; Copy B: pixel p at slot p+2 (64B shifted).
// HSZ_H = halfs per head per copy; VHALF = offset of copy B (halfs).
#define HSZ_H (16324 * 32)
#define VHALF (8 * HSZ_H)

// Scratch (device globals)
__device__ __half g_value[16 * HSZ_H];     // 2 copies x 8 heads
__device__ float  g_proj [LQ * PROJN];
__device__ __half g_mid  [LQ * DIM];

// ---------------- FP16 tensor-core GEMM (R8 form, m16n8k16) ----------------
// C = A(M x 256) * B(256 x N) + bias, fp32 accum. Block tile 64x128, BK=32.
// 256 threads = 8 warps (2x4), warp tile 32x32 = 2x4 m16n8k16 atoms.
#define GBM 64
#define GBN 128
#define AROW 40    // halfs per A row (32 + 8 pad)
#define BROW 136   // halfs per B row (128 + 8 pad)

struct Seg {
    const void*  A;      // float* or __half* (template)
    const float* B;
    const float* bias;
    float*  Cf;
    __half* Ch;
    int ldb, boff, ldc, cn0, ishalf;
};
struct SegArr { Seg s[8]; };

__device__ __forceinline__ uint32_t pack2(float a, float b) {
    __half2 h = __floats2half2_rn(a, b);
    return *(uint32_t*)&h;
}
__device__ __forceinline__ uint4 pack8(float4 v0, float4 v1) {
    uint4 u;
    u.x = pack2(v0.x, v0.y); u.y = pack2(v0.z, v0.w);
    u.z = pack2(v1.x, v1.y); u.w = pack2(v1.z, v1.w);
    return u;
}
__device__ __forceinline__ void ldsm4(uint32_t* r, uint32_t addr) {
    asm volatile("ldmatrix.sync.aligned.m8n8.x4.shared.b16 {%0,%1,%2,%3}, [%4];"
        : "=r"(r[0]), "=r"(r[1]), "=r"(r[2]), "=r"(r[3]) : "r"(addr));
}
__device__ __forceinline__ void ldsm4t(uint32_t* r, uint32_t addr) {
    asm volatile("ldmatrix.sync.aligned.m8n8.x4.trans.shared.b16 {%0,%1,%2,%3}, [%4];"
        : "=r"(r[0]), "=r"(r[1]), "=r"(r[2]), "=r"(r[3]) : "r"(addr));
}

template <typename AT>
__global__ __launch_bounds__(256) void mma_gemm_seg(SegArr sa)
{
    __shared__ __half As[64 * AROW];
    __shared__ __half Bs[32 * BROW];

    const Seg sg = sa.s[blockIdx.x];
    const int tid = threadIdx.x;
    const int bm  = blockIdx.y * GBM;

    const int lane = tid & 31, wid = tid >> 5;
    const int wm = wid >> 2, wn = wid & 3;
    const int g = lane >> 2, t = lane & 3;

    // ---- fill mappings ----
    const int ar = tid >> 2;            // A row 0..63
    const int ak = (tid & 3) << 3;      // A col octet base
    const AT* Ag = (const AT*)sg.A + (size_t)(bm + ar) * 256 + ak;
    __half* As_st = As + ar * AROW + ak;

    const int bkr = tid >> 5;           // B k-row 0..7 (x4 iters of +8)
    const int bn  = (tid & 31) << 2;    // B col quad
    const float* Bg = sg.B + (size_t)bkr * sg.ldb + sg.boff + bn;
    __half* Bs_st = Bs + bkr * BROW + bn;

    // ---- ldmatrix lane addresses ----
    const uint32_t as_addr = (uint32_t)__cvta_generic_to_shared(As);
    const uint32_t bs_addr = (uint32_t)__cvta_generic_to_shared(Bs);
    const int arow = wm * 32 + (lane & 7) + ((lane >> 3) & 1) * 8;  // + mi*16
    const int acol = (lane >> 4) * 8;                                // + ks*16
    const int brow = (lane & 7) + ((lane >> 3) & 1) * 8;             // + ks*16
    const int bcol = wn * 32 + (lane >> 4) * 8;                      // + nip*16
    const uint32_t aaddr0 = as_addr + (uint32_t)((arow * AROW + acol) * 2);
    const uint32_t baddr0 = bs_addr + (uint32_t)((brow * BROW + bcol) * 2);

    float acc[2][4][4] = {};

    // prefetch slab 0
    uint4 a_st;
    float4 bv[4];
    if constexpr (sizeof(AT) == 4) {
        float4 v0 = *(const float4*)(Ag);
        float4 v1 = *(const float4*)(Ag + 4);
        a_st = pack8(v0, v1);
    } else {
        a_st = *(const uint4*)(Ag);
    }
    #pragma unroll
    for (int it = 0; it < 4; ++it)
        bv[it] = *(const float4*)(Bg + (size_t)(it * 8) * sg.ldb);

    #pragma unroll
    for (int k0 = 0; k0 < 256; k0 += 32) {
        *(uint4*)As_st = a_st;
        #pragma unroll
        for (int it = 0; it < 4; ++it) {
            uint2 p; p.x = pack2(bv[it].x, bv[it].y); p.y = pack2(bv[it].z, bv[it].w);
            *(uint2*)(Bs_st + it * 8 * BROW) = p;
        }
        __syncthreads();

        if (k0 < 224) {
            if constexpr (sizeof(AT) == 4) {
                float4 v0 = *(const float4*)(Ag + k0 + 32);
                float4 v1 = *(const float4*)(Ag + k0 + 36);
                a_st = pack8(v0, v1);
            } else {
                a_st = *(const uint4*)(Ag + k0 + 32);
            }
            #pragma unroll
            for (int it = 0; it < 4; ++it)
                bv[it] = *(const float4*)(Bg + (size_t)(k0 + 32 + it * 8) * sg.ldb);
        }

        #pragma unroll
        for (int ks = 0; ks < 2; ++ks) {
            uint32_t a[2][4], b[2][4];
            #pragma unroll
            for (int mi = 0; mi < 2; ++mi)
                ldsm4(a[mi], aaddr0 + (uint32_t)((mi * 16 * AROW + ks * 16) * 2));
            #pragma unroll
            for (int nip = 0; nip < 2; ++nip)
                ldsm4t(b[nip], baddr0 + (uint32_t)((ks * 16 * BROW + nip * 16) * 2));
            #pragma unroll
            for (int mi = 0; mi < 2; ++mi)
                #pragma unroll
                for (int ni = 0; ni < 4; ++ni) {
                    uint32_t b0 = b[ni >> 1][(ni & 1) * 2];
                    uint32_t b1 = b[ni >> 1][(ni & 1) * 2 + 1];
                    asm volatile(
                        "mma.sync.aligned.m16n8k16.row.col.f32.f16.f16.f32 "
                        "{%0,%1,%2,%3}, {%4,%5,%6,%7}, {%8,%9}, {%0,%1,%2,%3};"
                        : "+f"(acc[mi][ni][0]), "+f"(acc[mi][ni][1]),
                          "+f"(acc[mi][ni][2]), "+f"(acc[mi][ni][3])
                        : "r"(a[mi][0]), "r"(a[mi][1]), "r"(a[mi][2]), "r"(a[mi][3]),
                          "r"(b0), "r"(b1));
                }
        }
        __syncthreads();
    }

    // ---- epilogue ----
    if (sg.ishalf) {
        // head-major dual-copy value write
        const int head = (sg.cn0 >> 5) + wn;
        __half* baseA = sg.Ch + (size_t)head * HSZ_H;
        __half* baseB = sg.Ch + (size_t)VHALF + (size_t)head * HSZ_H;
        #pragma unroll
        for (int mi = 0; mi < 2; ++mi) {
            int row0 = bm + wm * 32 + mi * 16 + g;
            #pragma unroll
            for (int ni = 0; ni < 4; ++ni) {
                int ch = ni * 8 + t * 2;
                __half2 h0 = __floats2half2_rn(acc[mi][ni][0], acc[mi][ni][1]);
                __half2 h1 = __floats2half2_rn(acc[mi][ni][2], acc[mi][ni][3]);
                *(__half2*)(baseA + (size_t)(row0 + 1) * 32 + ch)     = h0;
                *(__half2*)(baseA + (size_t)(row0 + 9) * 32 + ch)     = h1;
                *(__half2*)(baseB + (size_t)(row0 + 2) * 32 + ch)     = h0;
                *(__half2*)(baseB + (size_t)(row0 + 10) * 32 + ch)    = h1;
            }
        }
        // zero pads of copy A (slot 0 and slot 16321) once
        if (blockIdx.x == 0 && blockIdx.y == 0) {
            int hh = tid >> 5, cc = tid & 31;
            sg.Ch[(size_t)hh * HSZ_H + cc] = __float2half(0.f);
            sg.Ch[(size_t)hh * HSZ_H + (size_t)16321 * 32 + cc] = __float2half(0.f);
        }
    } else {
        #pragma unroll
        for (int mi = 0; mi < 2; ++mi) {
            int row0 = bm + wm * 32 + mi * 16 + g;
            #pragma unroll
            for (int ni = 0; ni < 4; ++ni) {
                int lcol = wn * 32 + ni * 8 + t * 2;
                float2 bv2 = *(const float2*)(sg.bias + sg.boff + lcol);
                float v00 = acc[mi][ni][0] + bv2.x, v01 = acc[mi][ni][1] + bv2.y;
                float v10 = acc[mi][ni][2] + bv2.x, v11 = acc[mi][ni][3] + bv2.y;
                *(float2*)(sg.Cf + (size_t)row0 * sg.ldc + sg.cn0 + lcol)       = make_float2(v00, v01);
                *(float2*)(sg.Cf + (size_t)(row0 + 8) * sg.ldc + sg.cn0 + lcol) = make_float2(v10, v11);
            }
        }
    }
}

// ---------------- Deformable sampling + softmax v4 ----------------
// Head-major dual-copy value: every (point, y-row) sample = one ALIGNED 128B
// load covering both x corners x 32 channels.
__global__ __launch_bounds__(256) void deform_kernel(
    const float* __restrict__ proj,
    const __half* __restrict__ value,
    const float* __restrict__ refp,
    const float* __restrict__ toff,
    __half* __restrict__ mid)
{
    __shared__ float4 smw[256];
    __shared__ int2   smb[256];

    const int q    = blockIdx.x;
    const int warp = threadIdx.x >> 5;
    const int lane = threadIdx.x & 31;
    const int h = warp;
    const int l = lane >> 3;
    const int p = lane & 7;

    const int   Wl[4]  = {64, 32, 16, 8};
    const int   THl[4] = {192, 96, 48, 24};
    const int   STl[4] = {0, 12288, 15360, 16128};
    const int   Wv = Wl[l], TH = THl[l], start = STl[l];
    const float invW = 1.0f / (float)Wv, invTH = 1.0f / (float)TH;

    const float* prow = proj + (size_t)q * PROJN;

    int logit_col = (p < 4) ? (512 + h * 16 + l * 4 + p)
                            : (640 + h * 16 + l * 4 + (p - 4));
    float logit = prow[logit_col];
    float mx = logit;
    #pragma unroll
    for (int off = 16; off; off >>= 1) mx = fmaxf(mx, __shfl_xor_sync(0xffffffffu, mx, off));
    float e = __expf(logit - mx);
    float s = e;
    #pragma unroll
    for (int off = 16; off; off >>= 1) s += __shfl_xor_sync(0xffffffffu, s, off);
    float attnw = e / s;

    float rx = refp[q * 8 + l * 2 + 0];
    float ry = refp[q * 8 + l * 2 + 1];
    float ox, oy;
    if (p < 4) {
        int col = ((h * 4 + l) * 4 + p) * 2;
        ox = prow[col + 0] * invW;
        oy = prow[col + 1] * invTH;
    } else {
        int tw = (p - 4) >> 1, tp = (p - 4) & 1;
        int col = 256 + (((h * 4 + l) * 2 + tw) * 2 + tp) * 2;
        int tob = ((q * 4 + l) * 2 + tw) * 2;
        ox = toff[tob + 0] + prow[col + 0] * invW;
        oy = toff[tob + 1] + prow[col + 1] * invTH;
    }
    float x = (rx + ox) * (float)Wv - 0.5f;
    float y = (ry + oy) * (float)TH - 0.5f;

    float x0f = floorf(x), y0f = floorf(y);
    float lx = x - x0f, ly = y - y0f;
    int x0 = (int)x0f, y0 = (int)y0f;
    int x1 = x0 + 1,   y1 = y0 + 1;

    bool ix0 = (x0 >= 0) & (x0 < Wv);
    bool ix1 = (x1 >= 0) & (x1 < Wv);
    bool iy0 = (y0 >= 0) & (y0 < TH);
    bool iy1 = (y1 >= 0) & (y1 < TH);
    int cy0 = min(max(y0, 0), TH - 1);
    int cy1 = min(max(y1, 0), TH - 1);

    float4 w;
    w.x = attnw * (1.f - lx) * (1.f - ly) * (float)(ix0 & iy0);   // (y0,x0)
    w.y = attnw * lx         * (1.f - ly) * (float)(ix1 & iy0);   // (y0,x1)
    w.z = attnw * (1.f - lx) * ly         * (float)(ix0 & iy1);   // (y1,x0)
    w.w = attnw * lx         * ly         * (float)(ix1 & iy1);   // (y1,x1)

    // dual-copy base: pick the copy where the (xb, xb+1) pair is 128B-aligned
    int xb   = min(max(x0, -1), Wv - 1);
    int odd  = xb & 1;                      // (-1)&1 = 1
    int shift = 1 + (odd ^ 1);              // slot shift: A=+1 (odd), B=+2 (even)
    int cbase = (odd ? 0 : VHALF) + h * HSZ_H;
    int pix0 = start + cy0 * Wv + xb;
    int pix1 = start + cy1 * Wv + xb;
    int2 bb;
    bb.x = cbase + (pix0 + shift) * 32;
    bb.y = cbase + (pix1 + shift) * 32;

    smw[threadIdx.x] = w;
    smb[threadIdx.x] = bb;
    __syncwarp();

    // ---- accumulate: lane = g(level)*8 + u; u: xs = u>>2, channel quad = u&3
    const int gg = lane >> 3;
    const int u  = lane & 7;
    const int xs = u >> 2;
    const int uoff = u << 3;     // halfs: 0..56 (16B per lane, 128B per group)

    float acc[8] = {};
    const int sbase = (warp << 5) + (gg << 3);
    #pragma unroll
    for (int pi = 0; pi < 8; ++pi) {
        float4 wv = smw[sbase + pi];
        int2  bp = smb[sbase + pi];
        float w0 = xs ? wv.y : wv.x;
        float w1 = xs ? wv.w : wv.z;
        uint4 v0 = __ldcg((const uint4*)(value + bp.x + uoff));
        uint4 v1 = __ldcg((const uint4*)(value + bp.y + uoff));
        float2 a0 = __half22float2(*(__half2*)&v0.x);
        float2 a1 = __half22float2(*(__half2*)&v0.y);
        float2 a2 = __half22float2(*(__half2*)&v0.z);
        float2 a3 = __half22float2(*(__half2*)&v0.w);
        float2 c0 = __half22float2(*(__half2*)&v1.x);
        float2 c1 = __half22float2(*(__half2*)&v1.y);
        float2 c2 = __half22float2(*(__half2*)&v1.z);
        float2 c3 = __half22float2(*(__half2*)&v1.w);
        acc[0] += w0 * a0.x + w1 * c0.x; acc[1] += w0 * a0.y + w1 * c0.y;
        acc[2] += w0 * a1.x + w1 * c1.x; acc[3] += w0 * a1.y + w1 * c1.y;
        acc[4] += w0 * a2.x + w1 * c2.x; acc[5] += w0 * a2.y + w1 * c2.y;
        acc[6] += w0 * a3.x + w1 * c3.x; acc[7] += w0 * a3.y + w1 * c3.y;
    }
    // reduce: xor4 = x corner, xor8/16 = level groups
    #pragma unroll
    for (int j = 0; j < 8; ++j) {
        acc[j] += __shfl_xor_sync(0xffffffffu, acc[j], 4);
        acc[j] += __shfl_xor_sync(0xffffffffu, acc[j], 8);
        acc[j] += __shfl_xor_sync(0xffffffffu, acc[j], 16);
    }
    if (lane < 4) {
        uint4 o8;
        o8.x = pack2(acc[0], acc[1]);
        o8.y = pack2(acc[2], acc[3]);
        o8.z = pack2(acc[4], acc[5]);
        o8.w = pack2(acc[6], acc[7]);
        *(uint4*)(mid + (size_t)q * DIM + warp * DHEAD + (lane << 3)) = o8;
    }
}

// ---------------- launch ----------------
extern "C" void kernel_launch(void* const* d_in, const int* in_sizes, int n_in,
                              void* d_out, int out_size)
{
    const float* query = (const float*)d_in[0];
    const float* refp  = (const float*)d_in[1];
    const float* toff  = (const float*)d_in[2];
    const float* inpf  = (const float*)d_in[3];
    const float* W_so  = (const float*)d_in[6];
    const float* b_so  = (const float*)d_in[7];
    const float* W_tso = (const float*)d_in[8];
    const float* b_tso = (const float*)d_in[9];
    const float* W_aw  = (const float*)d_in[10];
    const float* b_aw  = (const float*)d_in[11];
    const float* W_taw = (const float*)d_in[12];
    const float* b_taw = (const float*)d_in[13];
    const float* W_v   = (const float*)d_in[14];
    const float* b_v   = (const float*)d_in[15];
    const float* W_o   = (const float*)d_in[16];
    const float* b_o   = (const float*)d_in[17];
    float* out = (float*)d_out;

    __half *value, *mid; float *proj;
    cudaGetSymbolAddress((void**)&value, g_value);
    cudaGetSymbolAddress((void**)&proj,  g_proj);
    cudaGetSymbolAddress((void**)&mid,   g_mid);

    const int MB = LQ / GBM;  // 255
    dim3 blk(256);

    // (1) fused value + projections GEMM (8 segments, fp32 A)
    {
        SegArr sa{};
        for (int i = 0; i < 2; ++i) {
            sa.s[i].A = inpf; sa.s[i].B = W_v; sa.s[i].bias = b_v;
            sa.s[i].Ch = value; sa.s[i].ldb = 256; sa.s[i].boff = i * 128;
            sa.s[i].ldc = DIM; sa.s[i].cn0 = i * 128; sa.s[i].ishalf = 1;
        }
        for (int i = 0; i < 2; ++i) {
            sa.s[2 + i].A = query; sa.s[2 + i].B = W_so; sa.s[2 + i].bias = b_so;
            sa.s[2 + i].Cf = proj; sa.s[2 + i].ldb = 256; sa.s[2 + i].boff = i * 128;
            sa.s[2 + i].ldc = PROJN; sa.s[2 + i].cn0 = i * 128; sa.s[2 + i].ishalf = 0;
            sa.s[4 + i].A = query; sa.s[4 + i].B = W_tso; sa.s[4 + i].bias = b_tso;
            sa.s[4 + i].Cf = proj; sa.s[4 + i].ldb = 256; sa.s[4 + i].boff = i * 128;
            sa.s[4 + i].ldc = PROJN; sa.s[4 + i].cn0 = 256 + i * 128; sa.s[4 + i].ishalf = 0;
        }
        sa.s[6].A = query; sa.s[6].B = W_aw; sa.s[6].bias = b_aw;
        sa.s[6].Cf = proj; sa.s[6].ldb = 128; sa.s[6].boff = 0;
        sa.s[6].ldc = PROJN; sa.s[6].cn0 = 512; sa.s[6].ishalf = 0;
        sa.s[7].A = query; sa.s[7].B = W_taw; sa.s[7].bias = b_taw;
        sa.s[7].Cf = proj; sa.s[7].ldb = 128; sa.s[7].boff = 0;
        sa.s[7].ldc = PROJN; sa.s[7].cn0 = 640; sa.s[7].ishalf = 0;
        mma_gemm_seg<float><<<dim3(8, MB), blk>>>(sa);
    }
    // (2) deform (writes fp16 mid)
    deform_kernel<<<LQ, 256>>>(proj, value, refp, toff, mid);
    // (3) out = mid @ W_o + b_o  (fp16 A)
    {
        SegArr sa{};
        for (int i = 0; i < 2; ++i) {
            sa.s[i].A = mid; sa.s[i].B = W_o; sa.s[i].bias = b_o;
            sa.s[i].Cf = out; sa.s[i].ldb = 256; sa.s[i].boff = i * 128;
            sa.s[i].ldc = DIM; sa.s[i].cn0 = i * 128; sa.s[i].ishalf = 0;
        }
        mma_gemm_seg<__half><<<dim3(2, MB), blk>>>(sa);
    }
}

// round 12
// speedup vs baseline: 1.1662x; 1.1219x over previous
#include <cuda_runtime.h>
#include <cuda_fp16.h>
#include <math.h>
#include <stdint.h>

// Problem constants (fixed by setup_inputs)
#define DIM   256
#define NHEAD 8
#define DHEAD 32
#define LQ    16320
#define PROJN 768
#define NQE   (LQ * DIM)          // 4177920

// Head-major value, two alignment copies (see deform v4).
#define HSZ_H (16324 * 32)
#define VHALF (8 * HSZ_H)

// fp16 weight buffer offsets (halfs)
#define WV_OFF   0
#define WSO_OFF  65536
#define WTSO_OFF 131072
#define WAW_OFF  196608
#define WTAW_OFF 229376
#define WO_OFF   262144
#define WTOT     327680

// Scratch (device globals)
__device__ __half g_value[16 * HSZ_H];
__device__ float  g_proj [LQ * PROJN];
__device__ __half g_mid  [LQ * DIM];
__device__ __half g_hq   [NQE];        // fp16 query
__device__ __half g_hi   [NQE];        // fp16 input_flatten
__device__ __half g_hw   [WTOT];       // fp16 weights

// ---------------- prep: fp32 -> fp16 one-pass convert ----------------
__device__ __forceinline__ uint32_t pack2(float a, float b) {
    __half2 h = __floats2half2_rn(a, b);
    return *(uint32_t*)&h;
}
__device__ __forceinline__ uint4 pack8(float4 v0, float4 v1) {
    uint4 u;
    u.x = pack2(v0.x, v0.y); u.y = pack2(v0.z, v0.w);
    u.z = pack2(v1.x, v1.y); u.w = pack2(v1.z, v1.w);
    return u;
}
__device__ __forceinline__ void cvt8(const float* s, __half* d) {
    float4 v0 = *(const float4*)(s);
    float4 v1 = *(const float4*)(s + 4);
    *(uint4*)d = pack8(v0, v1);
}

__global__ __launch_bounds__(256) void prep_kernel(
    const float* __restrict__ q, const float* __restrict__ inp,
    const float* __restrict__ wv, const float* __restrict__ wso,
    const float* __restrict__ wtso, const float* __restrict__ waw,
    const float* __restrict__ wtaw, const float* __restrict__ wo,
    __half* __restrict__ hq, __half* __restrict__ hi, __half* __restrict__ hw)
{
    int base = (blockIdx.x * 256 + threadIdx.x) * 8;
    if (base < NQE) {
        cvt8(q + base, hq + base);
    } else if (base < 2 * NQE) {
        int b = base - NQE;
        cvt8(inp + b, hi + b);
    } else {
        int b = base - 2 * NQE;
        if (b < WTOT) {
            const float* src; int off;
            if      (b < WSO_OFF)  { src = wv;   off = b; }
            else if (b < WTSO_OFF) { src = wso;  off = b - WSO_OFF; }
            else if (b < WAW_OFF)  { src = wtso; off = b - WTSO_OFF; }
            else if (b < WTAW_OFF) { src = waw;  off = b - WAW_OFF; }
            else if (b < WO_OFF)   { src = wtaw; off = b - WTAW_OFF; }
            else                   { src = wo;   off = b - WO_OFF; }
            cvt8(src + off, hw + b);
        }
    }
}

// ---------------- FP16 GEMM v6: cp.async 3-stage pipeline ----------------
// C = A(M x 256) * B(256 x N) + bias, fp32 accum. Block tile 64x128, BK=32.
// All operands fp16 in gmem; smem filled via cp.async.cg (16B), no cvt.
#define GBM 64
#define GBN 128
#define AROW 40
#define BROW 136
#define ABUFB (64 * AROW * 2)   // bytes/stage
#define BBUFB (32 * BROW * 2)

struct Seg {
    const __half* A;
    const __half* B;
    const float*  bias;
    float*  Cf;
    __half* Ch;
    int ldb, boff, ldc, cn0, ishalf;
};
struct SegArr { Seg s[8]; };

__device__ __forceinline__ void cp16(uint32_t dst, const void* src) {
    asm volatile("cp.async.cg.shared.global [%0], [%1], 16;" :: "r"(dst), "l"(src));
}
__device__ __forceinline__ void ldsm4(uint32_t* r, uint32_t addr) {
    asm volatile("ldmatrix.sync.aligned.m8n8.x4.shared.b16 {%0,%1,%2,%3}, [%4];"
        : "=r"(r[0]), "=r"(r[1]), "=r"(r[2]), "=r"(r[3]) : "r"(addr));
}
__device__ __forceinline__ void ldsm4t(uint32_t* r, uint32_t addr) {
    asm volatile("ldmatrix.sync.aligned.m8n8.x4.trans.shared.b16 {%0,%1,%2,%3}, [%4];"
        : "=r"(r[0]), "=r"(r[1]), "=r"(r[2]), "=r"(r[3]) : "r"(addr));
}

__global__ __launch_bounds__(256) void mma_gemm_v6(SegArr sa)
{
    __shared__ __half As[3][64 * AROW];
    __shared__ __half Bs[3][32 * BROW];

    const Seg sg = sa.s[blockIdx.x];
    const int tid = threadIdx.x;
    const int bm  = blockIdx.y * GBM;

    const int lane = tid & 31, wid = tid >> 5;
    const int wm = wid >> 2, wn = wid & 3;
    const int g = lane >> 2, t = lane & 3;

    // cp.async source/dst mappings
    const __half* Agp = sg.A + (size_t)(bm + (tid >> 2)) * 256 + ((tid & 3) << 3);
    const __half* Bgp0 = sg.B + (size_t)(tid >> 4) * sg.ldb + sg.boff + ((tid & 15) << 3);
    const __half* Bgp1 = Bgp0 + (size_t)16 * sg.ldb;
    const uint32_t as0 = (uint32_t)__cvta_generic_to_shared(&As[0][0]) +
                         (((tid >> 2) * AROW + ((tid & 3) << 3)) << 1);
    const uint32_t bs0 = (uint32_t)__cvta_generic_to_shared(&Bs[0][0]) +
                         (((tid >> 4) * BROW + ((tid & 15) << 3)) << 1);
    const uint32_t bs1 = bs0 + 16 * BROW * 2;

    // ldmatrix lane addresses
    const uint32_t as_base = (uint32_t)__cvta_generic_to_shared(&As[0][0]);
    const uint32_t bs_base = (uint32_t)__cvta_generic_to_shared(&Bs[0][0]);
    const int arow = wm * 32 + (lane & 7) + ((lane >> 3) & 1) * 8;
    const int acol = (lane >> 4) * 8;
    const int brow = (lane & 7) + ((lane >> 3) & 1) * 8;
    const int bcol = wn * 32 + (lane >> 4) * 8;
    const uint32_t aaddr0 = as_base + (uint32_t)((arow * AROW + acol) * 2);
    const uint32_t baddr0 = bs_base + (uint32_t)((brow * BROW + bcol) * 2);

    float acc[2][4][4] = {};

    // prologue: issue stages 0,1
    #pragma unroll
    for (int s = 0; s < 2; ++s) {
        const int k0 = s * 32;
        cp16(as0 + s * ABUFB, Agp + k0);
        cp16(bs0 + s * BBUFB, Bgp0 + (size_t)k0 * sg.ldb);
        cp16(bs1 + s * BBUFB, Bgp1 + (size_t)k0 * sg.ldb);
        asm volatile("cp.async.commit_group;");
    }

    #pragma unroll
    for (int s = 0; s < 8; ++s) {
        if (s < 7) asm volatile("cp.async.wait_group 1;");
        else       asm volatile("cp.async.wait_group 0;");
        __syncthreads();

        if (s + 2 < 8) {
            const int st = (s + 2) % 3;
            const int k0 = (s + 2) * 32;
            cp16(as0 + st * ABUFB, Agp + k0);
            cp16(bs0 + st * BBUFB, Bgp0 + (size_t)k0 * sg.ldb);
            cp16(bs1 + st * BBUFB, Bgp1 + (size_t)k0 * sg.ldb);
            asm volatile("cp.async.commit_group;");
        }

        const int cur = s % 3;
        const uint32_t ab = aaddr0 + (uint32_t)(cur * ABUFB);
        const uint32_t bb = baddr0 + (uint32_t)(cur * BBUFB);
        #pragma unroll
        for (int ks = 0; ks < 2; ++ks) {
            uint32_t a[2][4], b[2][4];
            #pragma unroll
            for (int mi = 0; mi < 2; ++mi)
                ldsm4(a[mi], ab + (uint32_t)((mi * 16 * AROW + ks * 16) * 2));
            #pragma unroll
            for (int nip = 0; nip < 2; ++nip)
                ldsm4t(b[nip], bb + (uint32_t)((ks * 16 * BROW + nip * 16) * 2));
            #pragma unroll
            for (int mi = 0; mi < 2; ++mi)
                #pragma unroll
                for (int ni = 0; ni < 4; ++ni) {
                    uint32_t b0 = b[ni >> 1][(ni & 1) * 2];
                    uint32_t b1 = b[ni >> 1][(ni & 1) * 2 + 1];
                    asm volatile(
                        "mma.sync.aligned.m16n8k16.row.col.f32.f16.f16.f32 "
                        "{%0,%1,%2,%3}, {%4,%5,%6,%7}, {%8,%9}, {%0,%1,%2,%3};"
                        : "+f"(acc[mi][ni][0]), "+f"(acc[mi][ni][1]),
                          "+f"(acc[mi][ni][2]), "+f"(acc[mi][ni][3])
                        : "r"(a[mi][0]), "r"(a[mi][1]), "r"(a[mi][2]), "r"(a[mi][3]),
                          "r"(b0), "r"(b1));
                }
        }
        if (s < 7) __syncthreads();
    }

    // ---- epilogue ----
    if (sg.ishalf) {
        const int head = (sg.cn0 >> 5) + wn;
        __half* baseA = sg.Ch + (size_t)head * HSZ_H;
        __half* baseB = sg.Ch + (size_t)VHALF + (size_t)head * HSZ_H;
        #pragma unroll
        for (int mi = 0; mi < 2; ++mi) {
            int row0 = bm + wm * 32 + mi * 16 + g;
            #pragma unroll
            for (int ni = 0; ni < 4; ++ni) {
                int ch = ni * 8 + t * 2;
                __half2 h0 = __floats2half2_rn(acc[mi][ni][0], acc[mi][ni][1]);
                __half2 h1 = __floats2half2_rn(acc[mi][ni][2], acc[mi][ni][3]);
                *(__half2*)(baseA + (size_t)(row0 + 1) * 32 + ch)  = h0;
                *(__half2*)(baseA + (size_t)(row0 + 9) * 32 + ch)  = h1;
                *(__half2*)(baseB + (size_t)(row0 + 2) * 32 + ch)  = h0;
                *(__half2*)(baseB + (size_t)(row0 + 10) * 32 + ch) = h1;
            }
        }
        if (blockIdx.x == 0 && blockIdx.y == 0) {
            int hh = tid >> 5, cc = tid & 31;
            sg.Ch[(size_t)hh * HSZ_H + cc] = __float2half(0.f);
            sg.Ch[(size_t)hh * HSZ_H + (size_t)16321 * 32 + cc] = __float2half(0.f);
        }
    } else {
        #pragma unroll
        for (int mi = 0; mi < 2; ++mi) {
            int row0 = bm + wm * 32 + mi * 16 + g;
            #pragma unroll
            for (int ni = 0; ni < 4; ++ni) {
                int lcol = wn * 32 + ni * 8 + t * 2;
                float2 bv2 = *(const float2*)(sg.bias + sg.boff + lcol);
                float v00 = acc[mi][ni][0] + bv2.x, v01 = acc[mi][ni][1] + bv2.y;
                float v10 = acc[mi][ni][2] + bv2.x, v11 = acc[mi][ni][3] + bv2.y;
                *(float2*)(sg.Cf + (size_t)row0 * sg.ldc + sg.cn0 + lcol)       = make_float2(v00, v01);
                *(float2*)(sg.Cf + (size_t)(row0 + 8) * sg.ldc + sg.cn0 + lcol) = make_float2(v10, v11);
            }
        }
    }
}

// ---------------- Deformable sampling + softmax v4 (unchanged) ------------
__global__ __launch_bounds__(256) void deform_kernel(
    const float* __restrict__ proj,
    const __half* __restrict__ value,
    const float* __restrict__ refp,
    const float* __restrict__ toff,
    __half* __restrict__ mid)
{
    __shared__ float4 smw[256];
    __shared__ int2   smb[256];

    const int q    = blockIdx.x;
    const int warp = threadIdx.x >> 5;
    const int lane = threadIdx.x & 31;
    const int h = warp;
    const int l = lane >> 3;
    const int p = lane & 7;

    const int   Wl[4]  = {64, 32, 16, 8};
    const int   THl[4] = {192, 96, 48, 24};
    const int   STl[4] = {0, 12288, 15360, 16128};
    const int   Wv = Wl[l], TH = THl[l], start = STl[l];
    const float invW = 1.0f / (float)Wv, invTH = 1.0f / (float)TH;

    const float* prow = proj + (size_t)q * PROJN;

    int logit_col = (p < 4) ? (512 + h * 16 + l * 4 + p)
                            : (640 + h * 16 + l * 4 + (p - 4));
    float logit = prow[logit_col];
    float mx = logit;
    #pragma unroll
    for (int off = 16; off; off >>= 1) mx = fmaxf(mx, __shfl_xor_sync(0xffffffffu, mx, off));
    float e = __expf(logit - mx);
    float s = e;
    #pragma unroll
    for (int off = 16; off; off >>= 1) s += __shfl_xor_sync(0xffffffffu, s, off);
    float attnw = e / s;

    float rx = refp[q * 8 + l * 2 + 0];
    float ry = refp[q * 8 + l * 2 + 1];
    float ox, oy;
    if (p < 4) {
        int col = ((h * 4 + l) * 4 + p) * 2;
        ox = prow[col + 0] * invW;
        oy = prow[col + 1] * invTH;
    } else {
        int tw = (p - 4) >> 1, tp = (p - 4) & 1;
        int col = 256 + (((h * 4 + l) * 2 + tw) * 2 + tp) * 2;
        int tob = ((q * 4 + l) * 2 + tw) * 2;
        ox = toff[tob + 0] + prow[col + 0] * invW;
        oy = toff[tob + 1] + prow[col + 1] * invTH;
    }
    float x = (rx + ox) * (float)Wv - 0.5f;
    float y = (ry + oy) * (float)TH - 0.5f;

    float x0f = floorf(x), y0f = floorf(y);
    float lx = x - x0f, ly = y - y0f;
    int x0 = (int)x0f, y0 = (int)y0f;
    int x1 = x0 + 1,   y1 = y0 + 1;

    bool ix0 = (x0 >= 0) & (x0 < Wv);
    bool ix1 = (x1 >= 0) & (x1 < Wv);
    bool iy0 = (y0 >= 0) & (y0 < TH);
    bool iy1 = (y1 >= 0) & (y1 < TH);
    int cy0 = min(max(y0, 0), TH - 1);
    int cy1 = min(max(y1, 0), TH - 1);

    float4 w;
    w.x = attnw * (1.f - lx) * (1.f - ly) * (float)(ix0 & iy0);
    w.y = attnw * lx         * (1.f - ly) * (float)(ix1 & iy0);
    w.z = attnw * (1.f - lx) * ly         * (float)(ix0 & iy1);
    w.w = attnw * lx         * ly         * (float)(ix1 & iy1);

    int xb   = min(max(x0, -1), Wv - 1);
    int odd  = xb & 1;
    int shift = 1 + (odd ^ 1);
    int cbase = (odd ? 0 : VHALF) + h * HSZ_H;
    int pix0 = start + cy0 * Wv + xb;
    int pix1 = start + cy1 * Wv + xb;
    int2 bb;
    bb.x = cbase + (pix0 + shift) * 32;
    bb.y = cbase + (pix1 + shift) * 32;

    smw[threadIdx.x] = w;
    smb[threadIdx.x] = bb;
    __syncwarp();

    const int gg = lane >> 3;
    const int u  = lane & 7;
    const int xs = u >> 2;
    const int uoff = u << 3;

    float acc[8] = {};
    const int sbase = (warp << 5) + (gg << 3);
    #pragma unroll
    for (int pi = 0; pi < 8; ++pi) {
        float4 wv = smw[sbase + pi];
        int2  bp = smb[sbase + pi];
        float w0 = xs ? wv.y : wv.x;
        float w1 = xs ? wv.w : wv.z;
        uint4 v0 = __ldcg((const uint4*)(value + bp.x + uoff));
        uint4 v1 = __ldcg((const uint4*)(value + bp.y + uoff));
        float2 a0 = __half22float2(*(__half2*)&v0.x);
        float2 a1 = __half22float2(*(__half2*)&v0.y);
        float2 a2 = __half22float2(*(__half2*)&v0.z);
        float2 a3 = __half22float2(*(__half2*)&v0.w);
        float2 c0 = __half22float2(*(__half2*)&v1.x);
        float2 c1 = __half22float2(*(__half2*)&v1.y);
        float2 c2 = __half22float2(*(__half2*)&v1.z);
        float2 c3 = __half22float2(*(__half2*)&v1.w);
        acc[0] += w0 * a0.x + w1 * c0.x; acc[1] += w0 * a0.y + w1 * c0.y;
        acc[2] += w0 * a1.x + w1 * c1.x; acc[3] += w0 * a1.y + w1 * c1.y;
        acc[4] += w0 * a2.x + w1 * c2.x; acc[5] += w0 * a2.y + w1 * c2.y;
        acc[6] += w0 * a3.x + w1 * c3.x; acc[7] += w0 * a3.y + w1 * c3.y;
    }
    #pragma unroll
    for (int j = 0; j < 8; ++j) {
        acc[j] += __shfl_xor_sync(0xffffffffu, acc[j], 4);
        acc[j] += __shfl_xor_sync(0xffffffffu, acc[j], 8);
        acc[j] += __shfl_xor_sync(0xffffffffu, acc[j], 16);
    }
    if (lane < 4) {
        uint4 o8;
        o8.x = pack2(acc[0], acc[1]);
        o8.y = pack2(acc[2], acc[3]);
        o8.z = pack2(acc[4], acc[5]);
        o8.w = pack2(acc[6], acc[7]);
        *(uint4*)(mid + (size_t)q * DIM + warp * DHEAD + (lane << 3)) = o8;
    }
}

// ---------------- launch ----------------
extern "C" void kernel_launch(void* const* d_in, const int* in_sizes, int n_in,
                              void* d_out, int out_size)
{
    const float* query = (const float*)d_in[0];
    const float* refp  = (const float*)d_in[1];
    const float* toff  = (const float*)d_in[2];
    const float* inpf  = (const float*)d_in[3];
    const float* W_so  = (const float*)d_in[6];
    const float* b_so  = (const float*)d_in[7];
    const float* W_tso = (const float*)d_in[8];
    const float* b_tso = (const float*)d_in[9];
    const float* W_aw  = (const float*)d_in[10];
    const float* b_aw  = (const float*)d_in[11];
    const float* W_taw = (const float*)d_in[12];
    const float* b_taw = (const float*)d_in[13];
    const float* W_v   = (const float*)d_in[14];
    const float* b_v   = (const float*)d_in[15];
    const float* W_o   = (const float*)d_in[16];
    const float* b_o   = (const float*)d_in[17];
    float* out = (float*)d_out;

    __half *value, *mid, *hq, *hi, *hw; float *proj;
    cudaGetSymbolAddress((void**)&value, g_value);
    cudaGetSymbolAddress((void**)&proj,  g_proj);
    cudaGetSymbolAddress((void**)&mid,   g_mid);
    cudaGetSymbolAddress((void**)&hq,    g_hq);
    cudaGetSymbolAddress((void**)&hi,    g_hi);
    cudaGetSymbolAddress((void**)&hw,    g_hw);

    const int MB = LQ / GBM;  // 255
    dim3 blk(256);

    // (0) fp32 -> fp16 prep
    {
        int nthr = (2 * NQE + WTOT) / 8;   // 1085440
        prep_kernel<<<nthr / 256, 256>>>(query, inpf, W_v, W_so, W_tso, W_aw, W_taw, W_o,
                                         hq, hi, hw);
    }
    // (1) fused value + projections GEMM (8 segments)
    {
        SegArr sa{};
        for (int i = 0; i < 2; ++i) {
            sa.s[i].A = hi; sa.s[i].B = hw + WV_OFF; sa.s[i].bias = b_v;
            sa.s[i].Ch = value; sa.s[i].ldb = 256; sa.s[i].boff = i * 128;
            sa.s[i].ldc = DIM; sa.s[i].cn0 = i * 128; sa.s[i].ishalf = 1;
        }
        for (int i = 0; i < 2; ++i) {
            sa.s[2 + i].A = hq; sa.s[2 + i].B = hw + WSO_OFF; sa.s[2 + i].bias = b_so;
            sa.s[2 + i].Cf = proj; sa.s[2 + i].ldb = 256; sa.s[2 + i].boff = i * 128;
            sa.s[2 + i].ldc = PROJN; sa.s[2 + i].cn0 = i * 128; sa.s[2 + i].ishalf = 0;
            sa.s[4 + i].A = hq; sa.s[4 + i].B = hw + WTSO_OFF; sa.s[4 + i].bias = b_tso;
            sa.s[4 + i].Cf = proj; sa.s[4 + i].ldb = 256; sa.s[4 + i].boff = i * 128;
            sa.s[4 + i].ldc = PROJN; sa.s[4 + i].cn0 = 256 + i * 128; sa.s[4 + i].ishalf = 0;
        }
        sa.s[6].A = hq; sa.s[6].B = hw + WAW_OFF; sa.s[6].bias = b_aw;
        sa.s[6].Cf = proj; sa.s[6].ldb = 128; sa.s[6].boff = 0;
        sa.s[6].ldc = PROJN; sa.s[6].cn0 = 512; sa.s[6].ishalf = 0;
        sa.s[7].A = hq; sa.s[7].B = hw + WTAW_OFF; sa.s[7].bias = b_taw;
        sa.s[7].Cf = proj; sa.s[7].ldb = 128; sa.s[7].boff = 0;
        sa.s[7].ldc = PROJN; sa.s[7].cn0 = 640; sa.s[7].ishalf = 0;
        mma_gemm_v6<<<dim3(8, MB), blk>>>(sa);
    }
    // (2) deform (writes fp16 mid)
    deform_kernel<<<LQ, 256>>>(proj, value, refp, toff, mid);
    // (3) out = mid @ W_o + b_o
    {
        SegArr sa{};
        for (int i = 0; i < 2; ++i) {
            sa.s[i].A = mid; sa.s[i].B = hw + WO_OFF; sa.s[i].bias = b_o;
            sa.s[i].Cf = out; sa.s[i].ldb = 256; sa.s[i].boff = i * 128;
            sa.s[i].ldc = DIM; sa.s[i].cn0 = i * 128; sa.s[i].ishalf = 0;
        }
        mma_gemm_v6<<<dim3(2, MB), blk>>>(sa);
    }
}